// round 3
// baseline (speedup 1.0000x reference)
#include <cuda_runtime.h>
#include <cstdint>

// PANNAcceptor symbol-stationary persistent kernel.
// out[b] = lin_w @ (W[x_{L-1}] ... W[x_0] e0) + lin_b
// A=100 symbols, N=256 states, B=128 batches, S=1024 max len (A,B,S read at runtime).
//
// Grid = A persistent CTAs; CTA a permanently holds W[a]:
//   rows 0..127   -> 128 KB shared memory
//   rows 128..255 -> 128 KB registers (512 thr x 64 regs, packed f32x2)
// h vectors (1 KB/batch) hop between home CTAs via global memory with a
// per-batch release/acquire progress counter. Each CTA processes its
// occurrences in ascending t -> deadlock-free.

#define NST 256
#define MAXB 128
#define TPB 512

typedef unsigned long long ull;

__device__ float g_h[MAXB][NST];
__device__ int   g_progress[MAXB];

// ---------------- helpers ----------------
__device__ __forceinline__ int ld_acq(const int* p) {
    int v;
    asm volatile("ld.acquire.gpu.global.s32 %0, [%1];" : "=r"(v) : "l"(p) : "memory");
    return v;
}
__device__ __forceinline__ void st_rel(int* p, int v) {
    asm volatile("st.release.gpu.global.s32 [%0], %1;" :: "l"(p), "r"(v) : "memory");
}
__device__ __forceinline__ float4 ldcv4(const float* p) {
    float4 v;
    asm volatile("ld.volatile.global.v4.f32 {%0,%1,%2,%3}, [%4];"
                 : "=f"(v.x), "=f"(v.y), "=f"(v.z), "=f"(v.w) : "l"(p) : "memory");
    return v;
}
__device__ __forceinline__ ull pk(float x, float y) {
    ull r; asm("mov.b64 %0, {%1,%2};" : "=l"(r) : "f"(x), "f"(y)); return r;
}
__device__ __forceinline__ ull f2fma(ull a, ull b, ull c) {
    ull d; asm("fma.rn.f32x2 %0, %1, %2, %3;" : "=l"(d) : "l"(a), "l"(b), "l"(c));
    return d;
}
__device__ __forceinline__ float upk_sum(ull a) {
    float x, y; asm("mov.b64 {%0,%1}, %2;" : "=f"(x), "=f"(y) : "l"(a));
    return x + y;
}

// dot of one row slice held as 4 packed ulls against packed h fragments
__device__ __forceinline__ float dot8p(const ull* w, ull hA01, ull hA23, ull hB01, ull hB23) {
    ull acc = f2fma(w[0], hA01, 0ull);
    acc = f2fma(w[1], hA23, acc);
    acc = f2fma(w[2], hB01, acc);
    acc = f2fma(w[3], hB23, acc);
    return upk_sum(acc);
}

// ---------------- init kernel ----------------
__global__ void pann_init(int B) {
    int b = blockIdx.x;
    if (b >= B) return;
    if (threadIdx.x < NST / 4) {
        float4 z = make_float4(0.f, 0.f, 0.f, 0.f);
        if (threadIdx.x == 0) z.x = 1.0f;   // one-hot state 0
        ((float4*)g_h[b])[threadIdx.x] = z;
    }
    if (threadIdx.x == 0) g_progress[b] = 0;
}

// ---------------- persistent symbol kernel ----------------
extern __shared__ float Wsm[];   // 128*256 floats = 128 KB (rows 0..127)

__global__ __launch_bounds__(TPB, 1)
void pann_symbol(const int* __restrict__ xs,
                 const int* __restrict__ lengths,
                 const float* __restrict__ W,
                 int B, int S)
{
    __shared__ float hnew[NST];
    __shared__ int   s_ready[MAXB];
    __shared__ int   s_cnt;

    const int sym  = blockIdx.x;
    const int tid  = threadIdx.x;
    const int warp = tid >> 5;
    const int lane = tid & 31;

    const float* Wa = W + (size_t)sym * (NST * NST);

    // --- load W rows 0..127 into smem (coalesced) ---
    for (int idx = tid; idx < 128 * NST / 4; idx += TPB)
        ((float4*)Wsm)[idx] = ((const float4*)Wa)[idx];

    // --- load W rows 128..255 into registers, packed f32x2 ---
    // warp w owns rows 128 + 8w .. +7; lane covers cols [4l,4l+4) and [128+4l,+4)
    ull wreg[32];
    #pragma unroll
    for (int j = 0; j < 8; ++j) {
        const float4* row = (const float4*)(Wa + (size_t)(128 + warp * 8 + j) * NST);
        float4 a = row[lane];        // cols 4l..4l+3
        float4 b = row[32 + lane];   // cols 128+4l..+3
        wreg[4 * j + 0] = pk(a.x, a.y);
        wreg[4 * j + 1] = pk(a.z, a.w);
        wreg[4 * j + 2] = pk(b.x, b.y);
        wreg[4 * j + 3] = pk(b.z, b.w);
    }

    // per-thread batch ownership for the scan
    const int  myb   = tid;
    const int  mylen = (myb < B) ? lengths[myb] : 0;
    const int* myxs  = xs + (size_t)myb * S;

    __syncthreads();

    for (int t = 0; t < S; ++t) {
        bool mywork = (myb < B) && (t < mylen) && (myxs[t] == sym);
        int cnt = __syncthreads_count(mywork);
        if (cnt == 0) continue;

        if (tid == 0) s_cnt = 0;
        __syncthreads();
        if (mywork) { int k = atomicAdd(&s_cnt, 1); s_ready[k] = myb; }
        __syncthreads();

        for (int k = 0; k < cnt; ++k) {
            const int b = s_ready[k];

            // wait for h_t (produced by previous step's home CTA)
            if (tid == 0) { while (ld_acq(&g_progress[b]) < t) { } }
            __syncthreads();

            // fetch h fragments (strong loads: bypass stale L1)
            const float* hb = g_h[b];
            float4 hA = ldcv4(hb + 4 * lane);
            float4 hB = ldcv4(hb + 128 + 4 * lane);
            const ull hA01 = pk(hA.x, hA.y), hA23 = pk(hA.z, hA.w);
            const ull hB01 = pk(hB.x, hB.y), hB23 = pk(hB.z, hB.w);

            // ---- 16 rows per warp: 8 from smem, 8 from regs; pair-reduced ----
            #pragma unroll
            for (int j = 0; j < 8; j += 2) {
                // smem rows warp*8+j, +j+1
                const float* r0 = Wsm + (warp * 8 + j) * NST;
                const float* r1 = r0 + NST;
                float4 a0 = *(const float4*)(r0 + 4 * lane);
                float4 b0 = *(const float4*)(r0 + 128 + 4 * lane);
                float4 a1 = *(const float4*)(r1 + 4 * lane);
                float4 b1 = *(const float4*)(r1 + 128 + 4 * lane);
                ull w0[4] = { pk(a0.x,a0.y), pk(a0.z,a0.w), pk(b0.x,b0.y), pk(b0.z,b0.w) };
                ull w1[4] = { pk(a1.x,a1.y), pk(a1.z,a1.w), pk(b1.x,b1.y), pk(b1.z,b1.w) };
                float sA = dot8p(w0, hA01, hA23, hB01, hB23);
                float sB = dot8p(w1, hA01, hA23, hB01, hB23);

                float sAx = __shfl_xor_sync(0xffffffffu, sA, 16);
                float sBx = __shfl_xor_sync(0xffffffffu, sB, 16);
                float v = (lane < 16) ? (sA + sAx) : (sB + sBx);
                v += __shfl_xor_sync(0xffffffffu, v, 8);
                v += __shfl_xor_sync(0xffffffffu, v, 4);
                v += __shfl_xor_sync(0xffffffffu, v, 2);
                v += __shfl_xor_sync(0xffffffffu, v, 1);
                if (lane == 0)  hnew[warp * 8 + j]     = v;
                if (lane == 16) hnew[warp * 8 + j + 1] = v;
            }
            #pragma unroll
            for (int j = 0; j < 8; j += 2) {
                // reg rows 128 + warp*8 + j, +j+1
                float sA = dot8p(&wreg[4 * j],     hA01, hA23, hB01, hB23);
                float sB = dot8p(&wreg[4 * j + 4], hA01, hA23, hB01, hB23);

                float sAx = __shfl_xor_sync(0xffffffffu, sA, 16);
                float sBx = __shfl_xor_sync(0xffffffffu, sB, 16);
                float v = (lane < 16) ? (sA + sAx) : (sB + sBx);
                v += __shfl_xor_sync(0xffffffffu, v, 8);
                v += __shfl_xor_sync(0xffffffffu, v, 4);
                v += __shfl_xor_sync(0xffffffffu, v, 2);
                v += __shfl_xor_sync(0xffffffffu, v, 1);
                if (lane == 0)  hnew[128 + warp * 8 + j]     = v;
                if (lane == 16) hnew[128 + warp * 8 + j + 1] = v;
            }
            __syncthreads();

            // publish h_{t+1}
            if (tid < NST / 4)
                ((float4*)g_h[b])[tid] = ((const float4*)hnew)[tid];
            __threadfence();
            __syncthreads();
            if (tid == 0) st_rel(&g_progress[b], t + 1);
        }
    }
}

// ---------------- head kernel ----------------
__global__ void pann_head(const float* __restrict__ lin_w,
                          const float* __restrict__ lin_b,
                          float* __restrict__ out)
{
    const int b    = blockIdx.x;
    const int warp = threadIdx.x >> 5;  // 0 or 1 -> output class k
    const int lane = threadIdx.x & 31;
    const float* hf = g_h[b];
    float s = 0.0f;
    #pragma unroll
    for (int i = lane; i < NST; i += 32)
        s += lin_w[warp * NST + i] * hf[i];
    s += __shfl_xor_sync(0xffffffffu, s, 16);
    s += __shfl_xor_sync(0xffffffffu, s, 8);
    s += __shfl_xor_sync(0xffffffffu, s, 4);
    s += __shfl_xor_sync(0xffffffffu, s, 2);
    s += __shfl_xor_sync(0xffffffffu, s, 1);
    if (lane == 0) out[b * 2 + warp] = s + lin_b[warp];
}

// ---------------- fallback (R1 streaming kernel) ----------------
__global__ __launch_bounds__(512, 1)
void pann_chain_kernel(const int* __restrict__ xs,
                       const int* __restrict__ lengths,
                       const float* __restrict__ W,
                       const float* __restrict__ lin_w,
                       const float* __restrict__ lin_b,
                       float* __restrict__ out,
                       int S)
{
    __shared__ float hbuf[2][NST];
    const int b = blockIdx.x, tid = threadIdx.x, warp = tid >> 5, lane = tid & 31;
    if (tid < NST) hbuf[0][tid] = (tid == 0) ? 1.0f : 0.0f;
    const int L = lengths[b];
    const int* xrow = xs + (size_t)b * S;
    __syncthreads();
    int cur = 0;
    const int i0 = warp * 16;
    for (int t = 0; t < L; ++t) {
        const int a = __ldg(xrow + t);
        const float* Wa = W + (size_t)a * (NST * NST);
        const float* hsrc = hbuf[cur];
        float* hdst = hbuf[cur ^ 1];
        const float4 hA = *(const float4*)(hsrc + lane * 4);
        const float4 hB = *(const float4*)(hsrc + 128 + lane * 4);
        #pragma unroll 4
        for (int r = 0; r < 16; ++r) {
            const int i = i0 + r;
            const float4* p = (const float4*)(Wa + (size_t)i * NST + lane * 4);
            const float4 wA = p[0];
            const float4 wB = p[32];
            float s = wA.x*hA.x + wA.y*hA.y + wA.z*hA.z + wA.w*hA.w
                    + wB.x*hB.x + wB.y*hB.y + wB.z*hB.z + wB.w*hB.w;
            s += __shfl_xor_sync(0xffffffffu, s, 16);
            s += __shfl_xor_sync(0xffffffffu, s, 8);
            s += __shfl_xor_sync(0xffffffffu, s, 4);
            s += __shfl_xor_sync(0xffffffffu, s, 2);
            s += __shfl_xor_sync(0xffffffffu, s, 1);
            if (lane == 0) hdst[i] = s;
        }
        __syncthreads();
        cur ^= 1;
    }
    const float* hf = hbuf[cur];
    if (warp < 2) {
        float s = 0.0f;
        #pragma unroll
        for (int i = lane; i < NST; i += 32) s += lin_w[warp * NST + i] * hf[i];
        s += __shfl_xor_sync(0xffffffffu, s, 16);
        s += __shfl_xor_sync(0xffffffffu, s, 8);
        s += __shfl_xor_sync(0xffffffffu, s, 4);
        s += __shfl_xor_sync(0xffffffffu, s, 2);
        s += __shfl_xor_sync(0xffffffffu, s, 1);
        if (lane == 0) out[b * 2 + warp] = s + lin_b[warp];
    }
}

extern "C" void kernel_launch(void* const* d_in, const int* in_sizes, int n_in,
                              void* d_out, int out_size)
{
    const int*   xs      = (const int*)d_in[0];
    const int*   lengths = (const int*)d_in[1];
    const float* W       = (const float*)d_in[2];
    const float* lin_w   = (const float*)d_in[3];
    const float* lin_b   = (const float*)d_in[4];
    float*       out     = (float*)d_out;

    const int B = in_sizes[1];
    const int S = in_sizes[0] / B;
    const int A = in_sizes[2] / (NST * NST);

    if (A >= 1 && A <= 148 && B <= MAXB) {
        static const size_t smem = 128 * NST * sizeof(float);  // 128 KB
        cudaFuncSetAttribute(pann_symbol, cudaFuncAttributeMaxDynamicSharedMemorySize,
                             (int)smem);
        pann_init<<<B, 64>>>(B);
        pann_symbol<<<A, TPB, smem>>>(xs, lengths, W, B, S);
        pann_head<<<B, 64>>>(lin_w, lin_b, out);
    } else {
        pann_chain_kernel<<<B, 512>>>(xs, lengths, W, lin_w, lin_b, out, S);
    }
}

// round 4
// speedup vs baseline: 2.3590x; 2.3590x over previous
#include <cuda_runtime.h>
#include <cstdint>

// PANNAcceptor: out[b] = lin_w @ (W[x_{L-1}] ... W[x_0] e0) + lin_b
// Round 4: 2-CTA cluster per batch, row-split matvec, mbarrier ping-pong
// handoff (cheap ~60-90cy wait instead of barrier.cluster's ~870cy).
// Each CTA ingests 128 KB/step -> doubles the per-batch step rate cap that
// bounds the straggler tail; bulk phase stays chip-L2-bandwidth-bound.

#define NST  256
#define TPB  512          // 16 warps; each warp owns 8 of this CTA's 128 rows
#define HALF 128

__device__ __forceinline__ uint32_t smem_u32(const void* p) {
    uint32_t a;
    asm("{ .reg .u64 t; cvta.to.shared.u64 t, %1; cvt.u32.u64 %0, t; }" : "=r"(a) : "l"(p));
    return a;
}
__device__ __forceinline__ uint32_t mapa_u32(uint32_t a, uint32_t rank) {
    uint32_t r;
    asm("mapa.shared::cluster.u32 %0, %1, %2;" : "=r"(r) : "r"(a), "r"(rank));
    return r;
}
__device__ __forceinline__ void st_remote_f32(uint32_t ra, float v) {
    asm volatile("st.shared::cluster.f32 [%0], %1;" :: "r"(ra), "f"(v) : "memory");
}
__device__ __forceinline__ void mbar_init(uint32_t a, uint32_t n) {
    asm volatile("mbarrier.init.shared.b64 [%0], %1;" :: "r"(a), "r"(n) : "memory");
}
__device__ __forceinline__ void mbar_arrive_local(uint32_t a) {
    asm volatile("mbarrier.arrive.release.cluster.shared::cta.b64 _, [%0];" :: "r"(a) : "memory");
}
__device__ __forceinline__ void mbar_arrive_remote(uint32_t ra) {
    asm volatile("mbarrier.arrive.release.cluster.shared::cluster.b64 _, [%0];" :: "r"(ra) : "memory");
}
__device__ __forceinline__ void mbar_wait(uint32_t a, int parity) {
    asm volatile(
        "{\n\t"
        ".reg .pred P;\n\t"
        "W_%=:\n\t"
        "mbarrier.try_wait.parity.acquire.cluster.shared::cta.b64 P, [%0], %1, 0x989680;\n\t"
        "@!P bra W_%=;\n\t"
        "}"
        :: "r"(a), "r"(parity) : "memory");
}
#define CLUSTER_SYNC_() do { \
    asm volatile("barrier.cluster.arrive.aligned;" ::: "memory"); \
    asm volatile("barrier.cluster.wait.aligned;" ::: "memory"); } while (0)

__global__ __launch_bounds__(TPB, 2)
__cluster_dims__(2, 1, 1)
void pann_pair_kernel(const int* __restrict__ xs,
                      const int* __restrict__ lengths,
                      const float* __restrict__ W,
                      const float* __restrict__ lin_w,
                      const float* __restrict__ lin_b,
                      float* __restrict__ out,
                      int S)
{
    __shared__ float hbuf[2][NST];                       // ping-pong full h
    __shared__ alignas(8) unsigned long long mbar[2];    // one per buffer

    const int tid  = threadIdx.x;
    const int warp = tid >> 5;
    const int lane = tid & 31;
    const int b    = blockIdx.x >> 1;

    uint32_t rank;
    asm("mov.u32 %0, %%cluster_ctarank;" : "=r"(rank));
    const uint32_t peer   = rank ^ 1u;
    const uint32_t hb_u32 = smem_u32(hbuf);
    const uint32_t mb_u32 = smem_u32(mbar);
    const uint32_t rem_h  = mapa_u32(hb_u32, peer);
    const uint32_t rem_mb = mapa_u32(mb_u32, peer);

    // Arrivals per phase per barrier: 2 lanes (0,16) x 16 warps x 2 CTAs = 64.
    if (tid == 0) { mbar_init(mb_u32, 64); mbar_init(mb_u32 + 8, 64); }

    // h0 = one-hot(state 0): each CTA fills its OWN full copy.
    if (tid < NST) hbuf[0][tid] = (tid == 0) ? 1.0f : 0.0f;

    CLUSTER_SYNC_();   // mbar init + h0 visible before any remote arrive

    const int  L    = lengths[b];
    const int* xrow = xs + (size_t)b * S;
    const int  row0 = (int)rank * HALF + warp * 8;   // this warp's 8 rows

    int par0 = 0, par1 = 0;

    for (int t = 0; t < L; ++t) {
        const int cur = t & 1;
        const int nxt = cur ^ 1;

        if (t) {   // wait for both halves of h_t (acquire: peer's DSMEM stores visible)
            if (cur) { mbar_wait(mb_u32 + 8, par1); par1 ^= 1; }
            else     { mbar_wait(mb_u32,     par0); par0 ^= 1; }
        }

        const int a = __ldg(xrow + t);
        const float* Wr = W + (size_t)a * (NST * NST);
        const float* hsrc = hbuf[cur];
        float* hdst = hbuf[nxt];
        const uint32_t rdst = rem_h + (uint32_t)nxt * (NST * 4);

        // lane's h slice: cols [4l,4l+4) and [128+4l,+4)
        const float4 hA = ((const float4*)hsrc)[lane];
        const float4 hB = ((const float4*)hsrc)[32 + lane];

        #pragma unroll
        for (int j = 0; j < 8; j += 2) {
            const float4* p0 = (const float4*)(Wr + (size_t)(row0 + j) * NST);
            const float4* p1 = (const float4*)(Wr + (size_t)(row0 + j + 1) * NST);
            const float4 a0 = p0[lane], b0 = p0[32 + lane];   // 512B contiguous/warp
            const float4 a1 = p1[lane], b1 = p1[32 + lane];

            float sA = a0.x*hA.x + a0.y*hA.y + a0.z*hA.z + a0.w*hA.w
                     + b0.x*hB.x + b0.y*hB.y + b0.z*hB.z + b0.w*hB.w;
            float sB = a1.x*hA.x + a1.y*hA.y + a1.z*hA.z + a1.w*hA.w
                     + b1.x*hB.x + b1.y*hB.y + b1.z*hB.z + b1.w*hB.w;

            // pair reduction: low half reduces row j, high half row j+1
            const float oA = __shfl_xor_sync(0xffffffffu, sA, 16);
            const float oB = __shfl_xor_sync(0xffffffffu, sB, 16);
            float v = (lane < 16) ? (sA + oA) : (sB + oB);
            v += __shfl_xor_sync(0xffffffffu, v, 8);
            v += __shfl_xor_sync(0xffffffffu, v, 4);
            v += __shfl_xor_sync(0xffffffffu, v, 2);
            v += __shfl_xor_sync(0xffffffffu, v, 1);

            if (lane == 0 || lane == 16) {
                const int r = row0 + j + (lane >> 4);
                hdst[r] = v;                                   // my copy
                st_remote_f32(rdst + (uint32_t)r * 4, v);      // peer's copy
            }
        }

        // per-warp arrivals (after this lane's stores; release orders them)
        if (lane == 0 || lane == 16) {
            const uint32_t off = (uint32_t)nxt * 8;
            mbar_arrive_local(mb_u32 + off);
            mbar_arrive_remote(rem_mb + off);
        }
    }

    // Final sync: all step-(L-1) stores/arrivals from both CTAs are visible.
    CLUSTER_SYNC_();

    // Linear head on rank 0 (holds full h_final in its own smem).
    if (rank == 0 && warp < 2) {
        const float* hf = hbuf[L & 1];
        const int k = warp;
        float s = 0.0f;
        #pragma unroll
        for (int i = lane; i < NST; i += 32)
            s += lin_w[k * NST + i] * hf[i];
        s += __shfl_xor_sync(0xffffffffu, s, 16);
        s += __shfl_xor_sync(0xffffffffu, s, 8);
        s += __shfl_xor_sync(0xffffffffu, s, 4);
        s += __shfl_xor_sync(0xffffffffu, s, 2);
        s += __shfl_xor_sync(0xffffffffu, s, 1);
        if (lane == 0) out[b * 2 + k] = s + lin_b[k];
    }
}

extern "C" void kernel_launch(void* const* d_in, const int* in_sizes, int n_in,
                              void* d_out, int out_size)
{
    const int*   xs      = (const int*)d_in[0];
    const int*   lengths = (const int*)d_in[1];
    const float* W       = (const float*)d_in[2];
    const float* lin_w   = (const float*)d_in[3];
    const float* lin_b   = (const float*)d_in[4];
    float*       out     = (float*)d_out;

    const int B = in_sizes[1];
    const int S = in_sizes[0] / B;

    pann_pair_kernel<<<2 * B, TPB>>>(xs, lengths, W, lin_w, lin_b, out, S);
}